// round 15
// baseline (speedup 1.0000x reference)
#include <cuda_runtime.h>
#include <stdint.h>

#define BATCH   64
#define NPB     16384
#define HALF    8192
#define KSEL    1000
#define NCLS    80
#define NBIN    4096
#define CANDMAX 2048
#define NT      512
#define E_CTAS  256
#define S_CTAS  128
#define G_CTAS  128
#define N_ITER  8
#define ROWS_PER_ITER (E_CTAS * NT)     // 131072 rows = 8 batches per wave

typedef unsigned long long u64;

__device__ unsigned g_fg[BATCH * NPB];       // fg float bits per row (4 MB)
__device__ u64      g_cand[2 * BATCH][KSEL]; // sorted top-1000 per half-batch
__device__ unsigned g_iter[N_ITER];          // extract wave completion counters
__device__ unsigned g_sel[BATCH];            // per-batch select completion (==2)

// out layout (f32): scores[64000*80] | batch_idx[64000] | boxes[64000*4]
#define BI_FOFF 5120000u
#define BX_FOFF 5184000u

__global__ void init_counters()
{
    int t = threadIdx.x;                     // 64 threads
    if (t < N_ITER) g_iter[t] = 0u;
    g_sel[t] = 0u;
}

// ---------------------------------------------------------------------------
// threshold search, 512 threads x 8 descending bins each
// ---------------------------------------------------------------------------
__device__ __forceinline__ void find_thresh512(
    const unsigned* hist, unsigned* warpsums, unsigned Kneed,
    unsigned* out_bin, unsigned* out_above, int tid)
{
    int base = NBIN - 1 - 8 * tid;
    unsigned c[8];
    unsigned tsum = 0;
    #pragma unroll
    for (int k = 0; k < 8; k++) { c[k] = hist[base - k]; tsum += c[k]; }

    unsigned v = tsum;
    #pragma unroll
    for (int d = 1; d < 32; d <<= 1) {
        unsigned n = __shfl_up_sync(0xFFFFFFFFu, v, d);
        if ((tid & 31) >= d) v += n;
    }
    if ((tid & 31) == 31) warpsums[tid >> 5] = v;   // 16 warps
    __syncthreads();
    if (tid < 32) {
        unsigned w = (tid < 16) ? warpsums[tid] : 0u;
        #pragma unroll
        for (int d = 1; d < 16; d <<= 1) {
            unsigned n = __shfl_up_sync(0xFFFFFFFFu, w, d);
            if (tid >= d) w += n;
        }
        if (tid < 16) warpsums[tid] = w;
    }
    __syncthreads();
    unsigned wpre = (tid >= 32) ? warpsums[(tid >> 5) - 1] : 0u;
    unsigned run  = wpre + v - tsum;               // count in strictly-higher bins

    #pragma unroll
    for (int k = 0; k < 8; k++) {
        if (run < Kneed && run + c[k] >= Kneed) {
            *out_bin = (unsigned)(base - k);
            *out_above = run;
        }
        run += c[k];
    }
    __syncthreads();
}

__device__ __forceinline__ unsigned count_greater(const u64* arr, u64 key)
{
    unsigned lo = 0, hi = KSEL;
    #pragma unroll
    for (int s = 0; s < 10; s++) {            // 2^10 = 1024 >= 1000
        if (lo < hi) {
            unsigned mid = (lo + hi) >> 1;
            if (arr[mid] > key) lo = mid + 1; else hi = mid;
        }
    }
    return lo;
}

// ---------------------------------------------------------------------------
// Persistent role-specialized kernel.
//  CTAs [0,256):   extract — ALL 8 wave loads prefetched (MLP 8), then
//                  per-wave write->fence->sync->signal.
//  CTAs [256,384): select for half-batch (cta-256)
//  CTAs [384,512): gather for half of batch's output rows
// Cross-CTA data produced within this launch is read with __ldcg (L2,
// coherent) -- __ldg/L1 is NOT coherent across SMs within a launch.
// ---------------------------------------------------------------------------
__global__ void __launch_bounds__(NT, 3)
mega_kernel(const float* __restrict__ scores,
            const float* __restrict__ boxes,
            float* __restrict__ out)
{
    __shared__ alignas(16) unsigned char pool[32896];
    __shared__ unsigned sh_warpsums[16];
    __shared__ unsigned s_bin1, s_above1, s_bin2, s_above2, s_ncand;

    const int cta = blockIdx.x;
    const int tid = threadIdx.x;

    // ===================== EXTRACT ROLE =====================
    if (cta < E_CTAS) {
        const int rbase = cta * NT + tid;
        // issue all 8 strided loads upfront: full memory-level parallelism
        float raw[8];
        #pragma unroll
        for (int k = 0; k < N_ITER; k++)
            raw[k] = __ldg(scores + (size_t)(k * ROWS_PER_ITER + rbase) * NCLS);

        // drain waves in order; store k waits only on raw[k]'s scoreboard
        #pragma unroll
        for (int k = 0; k < N_ITER; k++) {
            g_fg[k * ROWS_PER_ITER + rbase] = __float_as_uint(1.0f - raw[k]);
            __threadfence();                    // release: visible at L2
            __syncthreads();
            if (tid == 0) atomicAdd(&g_iter[k], 1u);
        }
        return;
    }

    // ===================== SELECT ROLE =====================
    if (cta < E_CTAS + S_CTAS) {
        unsigned* sh_hist = (unsigned*)pool;                 // 16 KB
        u64*      sh_cand = (u64*)(pool + 16384);            // 16 KB

        const int hb   = cta - E_CTAS;        // half-batch [0,128)
        const int b    = hb >> 1;
        const int rk   = hb & 1;
        const int lane = tid & 31;
        const int wave = b >> 3;              // extract wave containing batch b

        for (int i = tid; i < NBIN; i += NT) sh_hist[i] = 0u;
        if (tid == 0) s_ncand = 0u;

        // wait for our extract wave (acquire)
        if (tid == 0) {
            while (atomicAdd(&g_iter[wave], 0u) < (unsigned)E_CTAS) __nanosleep(200);
            __threadfence();
        }
        __syncthreads();

        // coherent (L2) load of 8192 fg bits: 16 per thread
        unsigned v[16];
        const uint4* src = (const uint4*)(g_fg + b * NPB + rk * HALF);
        #pragma unroll
        for (int c = 0; c < 4; c++) {
            uint4 x = __ldcg(src + c * NT + tid);
            v[c * 4 + 0] = x.x; v[c * 4 + 1] = x.y;
            v[c * 4 + 2] = x.z; v[c * 4 + 3] = x.w;
        }

        // level-1 histogram
        #pragma unroll
        for (int q = 0; q < 16; q++)
            atomicAdd(&sh_hist[v[q] >> 20], 1u);
        __syncthreads();
        find_thresh512(sh_hist, sh_warpsums, KSEL, &s_bin1, &s_above1, tid);
        unsigned bin1 = s_bin1, above1 = s_above1;

        // level-2 histogram within bin1
        for (int i = tid; i < NBIN; i += NT) sh_hist[i] = 0u;
        __syncthreads();
        #pragma unroll
        for (int q = 0; q < 16; q++)
            if ((v[q] >> 20) == bin1) atomicAdd(&sh_hist[(v[q] >> 8) & 0xFFFu], 1u);
        __syncthreads();
        find_thresh512(sh_hist, sh_warpsums, KSEL - above1, &s_bin2, &s_above2, tid);
        unsigned t24 = (bin1 << 12) | s_bin2;

        // collect (warp-aggregated). key = bits<<32 | (NPB-1-idx) -> jax tie-break
        #pragma unroll
        for (int c = 0; c < 4; c++) {
            #pragma unroll
            for (int j = 0; j < 4; j++) {
                unsigned u = v[c * 4 + j];
                bool pred = ((u >> 8) >= t24);
                unsigned mask = __ballot_sync(0xFFFFFFFFu, pred);
                if (mask) {
                    int leader = __ffs(mask) - 1;
                    unsigned basep = 0;
                    if (lane == leader) basep = atomicAdd(&s_ncand, (unsigned)__popc(mask));
                    basep = __shfl_sync(0xFFFFFFFFu, basep, leader);
                    if (pred) {
                        unsigned off = basep + (unsigned)__popc(mask & ((1u << lane) - 1u));
                        if (off < CANDMAX) {
                            int idx = rk * HALF + (c * NT + tid) * 4 + j;
                            sh_cand[off] = ((u64)u << 32) | (u64)(unsigned)(NPB - 1 - idx);
                        }
                    }
                }
            }
        }
        __syncthreads();
        unsigned nc = s_ncand < CANDMAX ? s_ncand : CANDMAX;
        unsigned SORT = (nc <= 1024u) ? 1024u : 2048u;
        for (unsigned i = tid; i < SORT; i += NT)
            if (i >= nc) sh_cand[i] = 0ull;

        // bitonic sort descending
        for (unsigned k = 2; k <= SORT; k <<= 1) {
            for (unsigned j = k >> 1; j > 0; j >>= 1) {
                __syncthreads();
                for (unsigned t = (unsigned)tid; t < (SORT >> 1); t += NT) {
                    unsigned mask = j - 1u;
                    unsigned i = ((t & ~mask) << 1) | (t & mask);
                    unsigned p = i | j;
                    u64 a = sh_cand[i], c = sh_cand[p];
                    bool desc = ((i & k) == 0u);
                    if (desc ? (a < c) : (a > c)) { sh_cand[i] = c; sh_cand[p] = a; }
                }
            }
        }
        __syncthreads();

        for (int i = tid; i < KSEL; i += NT)
            g_cand[hb][i] = sh_cand[i];
        __threadfence();                          // release
        __syncthreads();
        if (tid == 0) atomicAdd(&g_sel[b], 1u);
        return;
    }

    // ===================== GATHER ROLE =====================
    {
        u64*      shA    = (u64*)pool;                       // 8000 B
        u64*      shB    = (u64*)(pool + 8000);              // 8000 B
        unsigned* sh_idx = (unsigned*)(pool + 16000);        // 4000 B

        const int gb   = cta - (E_CTAS + S_CTAS);            // [0,128)
        const int b    = gb >> 1;
        const int part = gb & 1;

        if (tid == 0) {
            while (atomicAdd(&g_sel[b], 0u) < 2u) __nanosleep(200);
            __threadfence();
        }
        __syncthreads();

        // coherent (L2) load of both sorted lists
        for (int i = tid; i < KSEL; i += NT) {
            shA[i] = __ldcg(&g_cand[2 * b][i]);
            shB[i] = __ldcg(&g_cand[2 * b + 1][i]);
        }
        __syncthreads();

        // exact global rank = own position + count-greater in the other list
        #pragma unroll
        for (int h = 0; h < 2; h++) {
            int i = tid + h * NT;
            if (i < KSEL) {
                u64 kA = shA[i];
                unsigned rA = (unsigned)i + count_greater(shB, kA);
                if (rA < KSEL) sh_idx[rA] = (NPB - 1u) - (unsigned)(kA & 0xFFFFull);
                u64 kB = shB[i];
                unsigned rB = (unsigned)i + count_greater(shA, kB);
                if (rB < KSEL) sh_idx[rB] = (NPB - 1u) - (unsigned)(kB & 0xFFFFull);
            }
        }
        __syncthreads();

        // gather ranks [part*500, part*500+500), 8 threads per row
        const int rbase = part * 500;
        const int q  = tid & 7;
        const int rw = tid >> 3;                  // 0..63
        #pragma unroll 1
        for (int it = 0; it < 4; it++) {
            int lA = it * 64 + rw;                // 0..255: always < 500
            int lB = lA + 256;                    // 256..511: guard < 500
            bool vB = lB < 500;
            unsigned ilA = sh_idx[rbase + lA];
            unsigned ilB = sh_idx[rbase + (vB ? lB : lA)];
            const float4* sA = (const float4*)(scores + ((size_t)b * NPB + ilA) * NCLS);
            const float4* sB = (const float4*)(scores + ((size_t)b * NPB + ilB) * NCLS);
            float4 a0 = __ldg(sA + q);
            float4 b0 = __ldg(sB + q);
            float4 a1 = __ldg(sA + q + 8);
            float4 b1 = __ldg(sB + q + 8);
            float4 a2, b2;
            if (q < 4) { a2 = __ldg(sA + 16 + q); b2 = __ldg(sB + 16 + q); }

            int rowA = rbase + lA;
            float4* dA = (float4*)(out + ((size_t)b * KSEL + rowA) * NCLS);
            dA[q]     = a0;
            dA[q + 8] = a1;
            if (q < 4) dA[16 + q] = a2;
            if (vB) {
                int rowB = rbase + lB;
                float4* dB = (float4*)(out + ((size_t)b * KSEL + rowB) * NCLS);
                dB[q]     = b0;
                dB[q + 8] = b1;
                if (q < 4) dB[16 + q] = b2;
            }
        }
        // boxes + batch index: one thread per row (500 rows per CTA)
        if (tid < 500) {
            int row = rbase + tid;
            unsigned il = sh_idx[row];
            size_t g = (size_t)b * NPB + il;
            size_t r = (size_t)b * KSEL + (size_t)row;
            float4 bx = __ldg((const float4*)(boxes + g * 4));
            *(float4*)(out + BX_FOFF + r * 4) = bx;
            out[BI_FOFF + r] = (float)b;
        }
    }
}

extern "C" void kernel_launch(void* const* d_in, const int* in_sizes, int n_in,
                              void* d_out, int out_size)
{
    const float* scores = (const float*)d_in[0];
    const float* boxes  = (const float*)d_in[2];
    float* out = (float*)d_out;

    init_counters<<<1, 64>>>();
    mega_kernel<<<E_CTAS + S_CTAS + G_CTAS, NT>>>(scores, boxes, out);
}

// round 16
// speedup vs baseline: 1.2945x; 1.2945x over previous
#include <cuda_runtime.h>
#include <stdint.h>

#define BATCH   64
#define NPB     16384
#define HALF    8192
#define KSEL    1000
#define NCLS    80
#define NBIN    4096
#define CANDMAX 2048

typedef unsigned long long u64;

__device__ u64 g_cand[2 * BATCH][KSEL];   // sorted top-1000 per half-batch

// out layout (f32): scores[64000*80] | batch_idx[64000] | boxes[64000*4]
#define BI_FOFF 5120000u
#define BX_FOFF 5184000u

// ---------------------------------------------------------------------------
// threshold search over 4096-bin histogram (descending), warp-shuffle scan
// (1024 threads, 4 bins each) — R9-proven
// ---------------------------------------------------------------------------
__device__ __forceinline__ void find_thresh(
    const unsigned* hist, unsigned* warpsums, unsigned Kneed,
    unsigned* out_bin, unsigned* out_above, int tid)
{
    int base = NBIN - 1 - 4 * tid;
    unsigned c0 = hist[base],     c1 = hist[base - 1];
    unsigned c2 = hist[base - 2], c3 = hist[base - 3];
    unsigned tsum = c0 + c1 + c2 + c3;

    unsigned v = tsum;
    #pragma unroll
    for (int d = 1; d < 32; d <<= 1) {
        unsigned n = __shfl_up_sync(0xFFFFFFFFu, v, d);
        if ((tid & 31) >= d) v += n;
    }
    if ((tid & 31) == 31) warpsums[tid >> 5] = v;
    __syncthreads();
    if (tid < 32) {
        unsigned w = warpsums[tid];
        #pragma unroll
        for (int d = 1; d < 32; d <<= 1) {
            unsigned n = __shfl_up_sync(0xFFFFFFFFu, w, d);
            if (tid >= d) w += n;
        }
        warpsums[tid] = w;
    }
    __syncthreads();
    unsigned wpre = (tid >= 32) ? warpsums[(tid >> 5) - 1] : 0u;
    unsigned run  = wpre + v - tsum;               // count in strictly-higher bins

    if (run < Kneed && run + c0 >= Kneed) { *out_bin = (unsigned)base;     *out_above = run; }
    run += c0;
    if (run < Kneed && run + c1 >= Kneed) { *out_bin = (unsigned)base - 1; *out_above = run; }
    run += c1;
    if (run < Kneed && run + c2 >= Kneed) { *out_bin = (unsigned)base - 2; *out_above = run; }
    run += c2;
    if (run < Kneed && run + c3 >= Kneed) { *out_bin = (unsigned)base - 3; *out_above = run; }
    __syncthreads();
}

// ---------------------------------------------------------------------------
// K1: one CTA per HALF-batch (128 CTAs x 1024). Strided extract (MLP 8),
// 2-level radix threshold, collect, register bitonic sort, write sorted list.
// ---------------------------------------------------------------------------
__global__ void __launch_bounds__(1024, 1)
half_select_kernel(const float* __restrict__ scores)
{
    __shared__ unsigned sh_hist[NBIN];      // 16 KB
    __shared__ u64      sh_cand[CANDMAX];   // 16 KB
    __shared__ unsigned sh_warpsums[32];
    __shared__ unsigned s_bin1, s_above1, s_bin2, s_above2, s_ncand;

    const int hb   = blockIdx.x;            // half-batch id [0,128)
    const int b    = hb >> 1;
    const int rk   = hb & 1;
    const int tid  = threadIdx.x;
    const int lane = tid & 31;

    // ---- extract: 8 independent strided column-0 loads ----
    const float* colbase = scores + ((size_t)b * NPB + (size_t)rk * HALF) * NCLS;
    float raw[8];
    #pragma unroll
    for (int q = 0; q < 8; q++)
        raw[q] = __ldg(colbase + (size_t)(q * 1024 + tid) * NCLS);

    for (int i = tid; i < NBIN; i += 1024) sh_hist[i] = 0u;
    if (tid == 0) s_ncand = 0u;
    __syncthreads();

    unsigned v[8];
    #pragma unroll
    for (int q = 0; q < 8; q++)
        v[q] = __float_as_uint(1.0f - raw[q]);   // positive floats: bits order-preserving

    // ---- level-1 histogram ----
    #pragma unroll
    for (int q = 0; q < 8; q++)
        atomicAdd(&sh_hist[v[q] >> 20], 1u);
    __syncthreads();
    find_thresh(sh_hist, sh_warpsums, KSEL, &s_bin1, &s_above1, tid);
    unsigned bin1 = s_bin1, above1 = s_above1;

    // ---- level-2 histogram within bin1 ----
    for (int i = tid; i < NBIN; i += 1024) sh_hist[i] = 0u;
    __syncthreads();
    #pragma unroll
    for (int q = 0; q < 8; q++)
        if ((v[q] >> 20) == bin1) atomicAdd(&sh_hist[(v[q] >> 8) & 0xFFFu], 1u);
    __syncthreads();
    find_thresh(sh_hist, sh_warpsums, KSEL - above1, &s_bin2, &s_above2, tid);
    unsigned t24 = (bin1 << 12) | s_bin2;

    // ---- collect candidates (warp-aggregated) ----
    // key = (bits<<32) | (NPB-1-idx): desc key == value desc, index asc (jax tie-break)
    #pragma unroll
    for (int q = 0; q < 8; q++) {
        unsigned u = v[q];
        bool pred = ((u >> 8) >= t24);
        unsigned mask = __ballot_sync(0xFFFFFFFFu, pred);
        if (mask) {
            int leader = __ffs(mask) - 1;
            unsigned basep = 0;
            if (lane == leader) basep = atomicAdd(&s_ncand, (unsigned)__popc(mask));
            basep = __shfl_sync(0xFFFFFFFFu, basep, leader);
            if (pred) {
                unsigned off = basep + (unsigned)__popc(mask & ((1u << lane) - 1u));
                if (off < CANDMAX) {
                    int idx = rk * HALF + q * 1024 + tid;     // index within batch
                    sh_cand[off] = ((u64)u << 32) | (u64)(unsigned)(NPB - 1 - idx);
                }
            }
        }
    }
    __syncthreads();
    unsigned nc = s_ncand < CANDMAX ? s_ncand : CANDMAX;

    if (nc <= 1024u) {
        // ---- fast path: register bitonic sort of 1024 (thread-per-element) ----
        // stages with j<32 are barrier-free via shfl_xor; j>=32 via smem.
        u64 r = ((unsigned)tid < nc) ? sh_cand[tid] : 0ull;
        #pragma unroll 1
        for (unsigned k = 2; k <= 1024u; k <<= 1) {
            #pragma unroll 1
            for (unsigned j = k >> 1; j > 0; j >>= 1) {
                u64 p;
                if (j >= 32u) {
                    __syncthreads();
                    sh_cand[tid] = r;
                    __syncthreads();
                    p = sh_cand[tid ^ j];
                } else {
                    p = __shfl_xor_sync(0xFFFFFFFFu, r, j);
                }
                bool lower   = ((tid & j) == 0u);        // I'm the lower index of the pair
                bool segDesc = ((tid & k) == 0u);        // this segment sorts descending
                bool takeMax = (segDesc == lower);
                u64 mx = (r > p) ? r : p;
                u64 mn = (r > p) ? p : r;
                r = takeMax ? mx : mn;
            }
        }
        if (tid < KSEL) g_cand[hb][tid] = r;
    } else {
        // ---- rare path: smem bitonic of 2048 (R9-proven) ----
        for (unsigned i = tid; i < CANDMAX; i += 1024)
            if (i >= nc) sh_cand[i] = 0ull;
        for (unsigned k = 2; k <= CANDMAX; k <<= 1) {
            for (unsigned j = k >> 1; j > 0; j >>= 1) {
                __syncthreads();
                unsigned mask = j - 1u;
                unsigned i = (((unsigned)tid & ~mask) << 1) | ((unsigned)tid & mask);
                unsigned p = i | j;
                u64 a = sh_cand[i], c = sh_cand[p];
                bool desc = ((i & k) == 0u);
                if (desc ? (a < c) : (a > c)) { sh_cand[i] = c; sh_cand[p] = a; }
            }
        }
        __syncthreads();
        if (tid < KSEL) g_cand[hb][tid] = sh_cand[tid];
    }
}

// ---------------------------------------------------------------------------
// K2: 4 CTAs per batch (256 CTAs x 512). 2-way sorted-list rank merge
// (exact, keys unique), then each CTA gathers 250 rows (4 thr/row, MLP 10).
// ---------------------------------------------------------------------------
__device__ __forceinline__ unsigned count_greater(const u64* arr, u64 key)
{
    unsigned lo = 0, hi = KSEL;
    #pragma unroll
    for (int s = 0; s < 10; s++) {            // 2^10 = 1024 >= 1000
        if (lo < hi) {
            unsigned mid = (lo + hi) >> 1;
            if (arr[mid] > key) lo = mid + 1; else hi = mid;
        }
    }
    return lo;
}

__global__ void __launch_bounds__(512)
merge_gather_kernel(const float* __restrict__ scores,
                    const float* __restrict__ boxes,
                    float* __restrict__ out)
{
    __shared__ u64      shA[KSEL];            // 8 KB
    __shared__ u64      shB[KSEL];            // 8 KB
    __shared__ unsigned sh_idx[KSEL];         // 4 KB: rank -> local row index

    const int b    = blockIdx.x >> 2;
    const int part = blockIdx.x & 3;
    const int tid  = threadIdx.x;

    for (int i = tid; i < KSEL; i += 512) {
        shA[i] = __ldg(&g_cand[2 * b][i]);
        shB[i] = __ldg(&g_cand[2 * b + 1][i]);
    }
    __syncthreads();

    // exact global rank = own position + count-greater in the other list
    #pragma unroll
    for (int h = 0; h < 2; h++) {
        int i = tid + h * 512;
        if (i < KSEL) {
            u64 kA = shA[i];
            unsigned rA = (unsigned)i + count_greater(shB, kA);
            if (rA < KSEL) sh_idx[rA] = (NPB - 1u) - (unsigned)(kA & 0xFFFFull);
            u64 kB = shB[i];
            unsigned rB = (unsigned)i + count_greater(shA, kB);
            if (rB < KSEL) sh_idx[rB] = (NPB - 1u) - (unsigned)(kB & 0xFFFFull);
        }
    }
    __syncthreads();

    // ---- gather ranks [part*250, part*250+250): 4 threads per row,
    //      both rows' 10 loads issued upfront (MLP 10) ----
    const int rbase = part * 250;
    const int q  = tid & 3;                   // float4 chunks q, q+4, ..., q+16
    const int rw = tid >> 2;                  // 0..127
    {
        int rA = rbase + rw;                  // rw < 128 < 250: always valid
        bool vB = (128 + rw) < 250;           // second row valid if rw < 122
        int rB = rbase + (vB ? 128 + rw : rw);
        unsigned ilA = sh_idx[rA];
        unsigned ilB = sh_idx[rB];
        const float4* sA = (const float4*)(scores + ((size_t)b * NPB + ilA) * NCLS);
        const float4* sB = (const float4*)(scores + ((size_t)b * NPB + ilB) * NCLS);
        float4 a[5], c[5];
        #pragma unroll
        for (int t = 0; t < 5; t++) a[t] = __ldg(sA + q + 4 * t);
        #pragma unroll
        for (int t = 0; t < 5; t++) c[t] = __ldg(sB + q + 4 * t);

        float4* dA = (float4*)(out + ((size_t)b * KSEL + rA) * NCLS);
        #pragma unroll
        for (int t = 0; t < 5; t++) dA[q + 4 * t] = a[t];
        if (vB) {
            float4* dB = (float4*)(out + ((size_t)b * KSEL + rB) * NCLS);
            #pragma unroll
            for (int t = 0; t < 5; t++) dB[q + 4 * t] = c[t];
        }
    }
    // boxes + batch index: one thread per row (250 rows per CTA)
    if (tid < 250) {
        int row = rbase + tid;
        unsigned il = sh_idx[row];
        size_t g = (size_t)b * NPB + il;
        size_t r = (size_t)b * KSEL + (size_t)row;
        float4 bx = __ldg((const float4*)(boxes + g * 4));
        *(float4*)(out + BX_FOFF + r * 4) = bx;
        out[BI_FOFF + r] = (float)b;
    }
}

extern "C" void kernel_launch(void* const* d_in, const int* in_sizes, int n_in,
                              void* d_out, int out_size)
{
    const float* scores = (const float*)d_in[0];
    const float* boxes  = (const float*)d_in[2];
    float* out = (float*)d_out;

    half_select_kernel<<<2 * BATCH, 1024>>>(scores);
    merge_gather_kernel<<<4 * BATCH, 512>>>(scores, boxes, out);
}

// round 17
// speedup vs baseline: 1.3086x; 1.0110x over previous
#include <cuda_runtime.h>
#include <stdint.h>

#define BATCH   64
#define NPB     16384
#define HALF    8192
#define KSEL    1000
#define NCLS    80
#define NBIN    4096
#define CANDMAX 2048

typedef unsigned long long u64;

__device__ u64 g_cand[2 * BATCH][KSEL];   // sorted top-1000 per half-batch

// out layout (f32): scores[64000*80] | batch_idx[64000] | boxes[64000*4]
#define BI_FOFF 5120000u
#define BX_FOFF 5184000u

// ---------------------------------------------------------------------------
// threshold search over 4096-bin histogram (descending), warp-shuffle scan
// (1024 threads, 4 bins each) — R9-proven
// ---------------------------------------------------------------------------
__device__ __forceinline__ void find_thresh(
    const unsigned* hist, unsigned* warpsums, unsigned Kneed,
    unsigned* out_bin, unsigned* out_above, int tid)
{
    int base = NBIN - 1 - 4 * tid;
    unsigned c0 = hist[base],     c1 = hist[base - 1];
    unsigned c2 = hist[base - 2], c3 = hist[base - 3];
    unsigned tsum = c0 + c1 + c2 + c3;

    unsigned v = tsum;
    #pragma unroll
    for (int d = 1; d < 32; d <<= 1) {
        unsigned n = __shfl_up_sync(0xFFFFFFFFu, v, d);
        if ((tid & 31) >= d) v += n;
    }
    if ((tid & 31) == 31) warpsums[tid >> 5] = v;
    __syncthreads();
    if (tid < 32) {
        unsigned w = warpsums[tid];
        #pragma unroll
        for (int d = 1; d < 32; d <<= 1) {
            unsigned n = __shfl_up_sync(0xFFFFFFFFu, w, d);
            if (tid >= d) w += n;
        }
        warpsums[tid] = w;
    }
    __syncthreads();
    unsigned wpre = (tid >= 32) ? warpsums[(tid >> 5) - 1] : 0u;
    unsigned run  = wpre + v - tsum;               // count in strictly-higher bins

    if (run < Kneed && run + c0 >= Kneed) { *out_bin = (unsigned)base;     *out_above = run; }
    run += c0;
    if (run < Kneed && run + c1 >= Kneed) { *out_bin = (unsigned)base - 1; *out_above = run; }
    run += c1;
    if (run < Kneed && run + c2 >= Kneed) { *out_bin = (unsigned)base - 2; *out_above = run; }
    run += c2;
    if (run < Kneed && run + c3 >= Kneed) { *out_bin = (unsigned)base - 3; *out_above = run; }
    __syncthreads();
}

// ---------------------------------------------------------------------------
// K1: one CTA per HALF-batch (128 CTAs x 1024). Strided extract (MLP 8),
// 2-level radix threshold, collect, register bitonic sort, write sorted list.
// ---------------------------------------------------------------------------
__global__ void __launch_bounds__(1024, 1)
half_select_kernel(const float* __restrict__ scores)
{
    __shared__ unsigned sh_hist[NBIN];      // 16 KB
    __shared__ u64      sh_cand[CANDMAX];   // 16 KB
    __shared__ unsigned sh_warpsums[32];
    __shared__ unsigned s_bin1, s_above1, s_bin2, s_above2, s_ncand;

    const int hb   = blockIdx.x;            // half-batch id [0,128)
    const int b    = hb >> 1;
    const int rk   = hb & 1;
    const int tid  = threadIdx.x;
    const int lane = tid & 31;

    // ---- extract: 8 independent strided column-0 loads ----
    const float* colbase = scores + ((size_t)b * NPB + (size_t)rk * HALF) * NCLS;
    float raw[8];
    #pragma unroll
    for (int q = 0; q < 8; q++)
        raw[q] = __ldg(colbase + (size_t)(q * 1024 + tid) * NCLS);

    for (int i = tid; i < NBIN; i += 1024) sh_hist[i] = 0u;
    if (tid == 0) s_ncand = 0u;
    __syncthreads();

    unsigned v[8];
    #pragma unroll
    for (int q = 0; q < 8; q++)
        v[q] = __float_as_uint(1.0f - raw[q]);   // positive floats: bits order-preserving

    // ---- level-1 histogram ----
    #pragma unroll
    for (int q = 0; q < 8; q++)
        atomicAdd(&sh_hist[v[q] >> 20], 1u);
    __syncthreads();
    find_thresh(sh_hist, sh_warpsums, KSEL, &s_bin1, &s_above1, tid);
    unsigned bin1 = s_bin1, above1 = s_above1;

    // ---- level-2 histogram within bin1 ----
    for (int i = tid; i < NBIN; i += 1024) sh_hist[i] = 0u;
    __syncthreads();
    #pragma unroll
    for (int q = 0; q < 8; q++)
        if ((v[q] >> 20) == bin1) atomicAdd(&sh_hist[(v[q] >> 8) & 0xFFFu], 1u);
    __syncthreads();
    find_thresh(sh_hist, sh_warpsums, KSEL - above1, &s_bin2, &s_above2, tid);
    unsigned t24 = (bin1 << 12) | s_bin2;

    // ---- collect candidates (warp-aggregated) ----
    // key = (bits<<32) | (NPB-1-idx): desc key == value desc, index asc (jax tie-break)
    #pragma unroll
    for (int q = 0; q < 8; q++) {
        unsigned u = v[q];
        bool pred = ((u >> 8) >= t24);
        unsigned mask = __ballot_sync(0xFFFFFFFFu, pred);
        if (mask) {
            int leader = __ffs(mask) - 1;
            unsigned basep = 0;
            if (lane == leader) basep = atomicAdd(&s_ncand, (unsigned)__popc(mask));
            basep = __shfl_sync(0xFFFFFFFFu, basep, leader);
            if (pred) {
                unsigned off = basep + (unsigned)__popc(mask & ((1u << lane) - 1u));
                if (off < CANDMAX) {
                    int idx = rk * HALF + q * 1024 + tid;     // index within batch
                    sh_cand[off] = ((u64)u << 32) | (u64)(unsigned)(NPB - 1 - idx);
                }
            }
        }
    }
    __syncthreads();
    unsigned nc = s_ncand < CANDMAX ? s_ncand : CANDMAX;

    if (nc <= 1024u) {
        // ---- fast path: register bitonic sort of 1024 (thread-per-element) ----
        // stages with j<32 are barrier-free via shfl_xor; j>=32 via smem.
        u64 r = ((unsigned)tid < nc) ? sh_cand[tid] : 0ull;
        #pragma unroll 1
        for (unsigned k = 2; k <= 1024u; k <<= 1) {
            #pragma unroll 1
            for (unsigned j = k >> 1; j > 0; j >>= 1) {
                u64 p;
                if (j >= 32u) {
                    __syncthreads();
                    sh_cand[tid] = r;
                    __syncthreads();
                    p = sh_cand[tid ^ j];
                } else {
                    p = __shfl_xor_sync(0xFFFFFFFFu, r, j);
                }
                bool lower   = ((tid & j) == 0u);        // I'm the lower index of the pair
                bool segDesc = ((tid & k) == 0u);        // this segment sorts descending
                bool takeMax = (segDesc == lower);
                u64 mx = (r > p) ? r : p;
                u64 mn = (r > p) ? p : r;
                r = takeMax ? mx : mn;
            }
        }
        if (tid < KSEL) g_cand[hb][tid] = r;
    } else {
        // ---- rare path: smem bitonic of 2048 (R9-proven) ----
        for (unsigned i = tid; i < CANDMAX; i += 1024)
            if (i >= nc) sh_cand[i] = 0ull;
        for (unsigned k = 2; k <= CANDMAX; k <<= 1) {
            for (unsigned j = k >> 1; j > 0; j >>= 1) {
                __syncthreads();
                unsigned mask = j - 1u;
                unsigned i = (((unsigned)tid & ~mask) << 1) | ((unsigned)tid & mask);
                unsigned p = i | j;
                u64 a = sh_cand[i], c = sh_cand[p];
                bool desc = ((i & k) == 0u);
                if (desc ? (a < c) : (a > c)) { sh_cand[i] = c; sh_cand[p] = a; }
            }
        }
        __syncthreads();
        if (tid < KSEL) g_cand[hb][tid] = sh_cand[tid];
    }
}

// ---------------------------------------------------------------------------
// K2: 4 CTAs per batch (256 CTAs x 512). 2-way sorted-list rank merge
// (exact, keys unique), then each CTA gathers 250 rows (4 thr/row, MLP 10).
// ---------------------------------------------------------------------------
__device__ __forceinline__ unsigned count_greater(const u64* arr, u64 key)
{
    unsigned lo = 0, hi = KSEL;
    #pragma unroll
    for (int s = 0; s < 10; s++) {            // 2^10 = 1024 >= 1000
        if (lo < hi) {
            unsigned mid = (lo + hi) >> 1;
            if (arr[mid] > key) lo = mid + 1; else hi = mid;
        }
    }
    return lo;
}

__global__ void __launch_bounds__(512)
merge_gather_kernel(const float* __restrict__ scores,
                    const float* __restrict__ boxes,
                    float* __restrict__ out)
{
    __shared__ u64      shA[KSEL];            // 8 KB
    __shared__ u64      shB[KSEL];            // 8 KB
    __shared__ unsigned sh_idx[KSEL];         // 4 KB: rank -> local row index

    const int b    = blockIdx.x >> 2;
    const int part = blockIdx.x & 3;
    const int tid  = threadIdx.x;

    for (int i = tid; i < KSEL; i += 512) {
        shA[i] = __ldg(&g_cand[2 * b][i]);
        shB[i] = __ldg(&g_cand[2 * b + 1][i]);
    }
    __syncthreads();

    // exact global rank = own position + count-greater in the other list
    #pragma unroll
    for (int h = 0; h < 2; h++) {
        int i = tid + h * 512;
        if (i < KSEL) {
            u64 kA = shA[i];
            unsigned rA = (unsigned)i + count_greater(shB, kA);
            if (rA < KSEL) sh_idx[rA] = (NPB - 1u) - (unsigned)(kA & 0xFFFFull);
            u64 kB = shB[i];
            unsigned rB = (unsigned)i + count_greater(shA, kB);
            if (rB < KSEL) sh_idx[rB] = (NPB - 1u) - (unsigned)(kB & 0xFFFFull);
        }
    }
    __syncthreads();

    // ---- gather ranks [part*250, part*250+250): 4 threads per row,
    //      both rows' 10 loads issued upfront (MLP 10) ----
    const int rbase = part * 250;
    const int q  = tid & 3;                   // float4 chunks q, q+4, ..., q+16
    const int rw = tid >> 2;                  // 0..127
    {
        int rA = rbase + rw;                  // rw < 128 < 250: always valid
        bool vB = (128 + rw) < 250;           // second row valid if rw < 122
        int rB = rbase + (vB ? 128 + rw : rw);
        unsigned ilA = sh_idx[rA];
        unsigned ilB = sh_idx[rB];
        const float4* sA = (const float4*)(scores + ((size_t)b * NPB + ilA) * NCLS);
        const float4* sB = (const float4*)(scores + ((size_t)b * NPB + ilB) * NCLS);
        float4 a[5], c[5];
        #pragma unroll
        for (int t = 0; t < 5; t++) a[t] = __ldg(sA + q + 4 * t);
        #pragma unroll
        for (int t = 0; t < 5; t++) c[t] = __ldg(sB + q + 4 * t);

        float4* dA = (float4*)(out + ((size_t)b * KSEL + rA) * NCLS);
        #pragma unroll
        for (int t = 0; t < 5; t++) dA[q + 4 * t] = a[t];
        if (vB) {
            float4* dB = (float4*)(out + ((size_t)b * KSEL + rB) * NCLS);
            #pragma unroll
            for (int t = 0; t < 5; t++) dB[q + 4 * t] = c[t];
        }
    }
    // boxes + batch index: one thread per row (250 rows per CTA)
    if (tid < 250) {
        int row = rbase + tid;
        unsigned il = sh_idx[row];
        size_t g = (size_t)b * NPB + il;
        size_t r = (size_t)b * KSEL + (size_t)row;
        float4 bx = __ldg((const float4*)(boxes + g * 4));
        *(float4*)(out + BX_FOFF + r * 4) = bx;
        out[BI_FOFF + r] = (float)b;
    }
}

extern "C" void kernel_launch(void* const* d_in, const int* in_sizes, int n_in,
                              void* d_out, int out_size)
{
    const float* scores = (const float*)d_in[0];
    const float* boxes  = (const float*)d_in[2];
    float* out = (float*)d_out;

    half_select_kernel<<<2 * BATCH, 1024>>>(scores);
    merge_gather_kernel<<<4 * BATCH, 512>>>(scores, boxes, out);
}